// round 10
// baseline (speedup 1.0000x reference)
#include <cuda_runtime.h>
#include <math.h>

#define NN   100000
#define EE   500000
#define DD   128
#define EFD  16
#define XDIM 272        // 2*DD + EFD
#define HH   2
#define HD   256        // HH * DD
#define OUTD 64

typedef unsigned long long u64;

// ---------------- scratch (device globals; no allocation allowed) ----------------
__device__ int      g_is64;
__device__ int      g_winner[NN];
__device__ __align__(16) float g_node_mem[(size_t)NN * DD];
__device__ __align__(16) float g_q[(size_t)NN * HD];
__device__ __align__(16) float g_k[(size_t)NN * HD];
__device__ __align__(16) float g_v[(size_t)NN * HD];
__device__ __align__(16) float g_logit[(size_t)EE * HH];   // exp(logit)
__device__ float    g_sum[NN * HH];
__device__ __align__(16) float g_agg[(size_t)NN * HD];
// K-paired weights: wp[k2][c] = {W[2k2][c], W[2k2+1][c]} as u64
__device__ __align__(16) u64   g_w1p[136 * 128];
__device__ __align__(16) u64   g_w2p[64 * 128];
__device__ __align__(16) u64   g_wip[64 * 384];   // gi weights (from wih[c][k])
__device__ __align__(16) u64   g_whp[64 * 384];   // gh weights (from whh[c][k])
__device__ __align__(16) u64   g_qkvp[64 * 768];  // cols 0-255 q, 256-511 k, 512-767 v
__device__ __align__(16) u64   g_wcp[128 * 64];
__device__ __align__(16) u64   g_wscp[64 * 64];   // paired wskip@wc
__device__ __align__(16) float g_bsc[OUTD];       // bskip@wc + bc

// edge_index accessor: dtype decided at runtime by k_detect
__device__ __forceinline__ int ld_idx(const void* ei, size_t i) {
    if (g_is64) return (int)((const long long*)ei)[i];
    return ((const int*)ei)[i];
}
__device__ __forceinline__ float4 ld4(const float* p) {
    return *reinterpret_cast<const float4*>(p);
}
// ---- packed f32x2 helpers ----
__device__ __forceinline__ u64 pack_pair(float lo, float hi) {
    u64 r; asm("mov.b64 %0,{%1,%2};" : "=l"(r) : "f"(lo), "f"(hi)); return r;
}
__device__ __forceinline__ void fma2(u64& a, u64 x, u64 w) {
    asm("fma.rn.f32x2 %0,%1,%2,%0;" : "+l"(a) : "l"(x), "l"(w));
}
__device__ __forceinline__ float2 unpack2(u64 a) {
    float2 f; asm("mov.b64 {%0,%1},%2;" : "=f"(f.x), "=f"(f.y) : "l"(a)); return f;
}
__device__ __forceinline__ u64 ldp(const float* p) {   // LDS/LDG .64 of two contiguous floats
    return *reinterpret_cast<const u64*>(p);
}
__device__ __forceinline__ void red4(float* addr, float a, float b, float c, float d) {
    asm volatile("red.global.add.v4.f32 [%0], {%1,%2,%3,%4};"
                 :: "l"(addr), "f"(a), "f"(b), "f"(c), "f"(d) : "memory");
}
// fast transcendentals (abs err ~1e-7 at these magnitudes)
__device__ __forceinline__ float sigm(float x) { return __fdividef(1.f, 1.f + __expf(-x)); }
__device__ __forceinline__ float tanh_f(float x) { return __fdividef(2.f, 1.f + __expf(-2.f * x)) - 1.f; }

// ---------------- dtype detect ----------------
__global__ void k_detect(const void* ei) {
    __shared__ int bad;
    int t = threadIdx.x;
    if (t == 0) bad = 0;
    __syncthreads();
    long long v = ((const long long*)ei)[t];
    if (v < 0 || v >= NN) atomicExch(&bad, 1);
    __syncthreads();
    if (t == 0) g_is64 = bad ? 0 : 1;
}

// ---------------- init ----------------
__global__ void k_init() {
    size_t i = (size_t)blockIdx.x * blockDim.x + threadIdx.x;
    if (i < (size_t)NN * HD) g_agg[i] = 0.f;
    if (i < NN) g_winner[i] = -1;
    if (i < (size_t)NN * HH) g_sum[i] = 0.f;
}

// ---------------- fold skip into classifier, write paired ----------------
__global__ void k_fusew(const float* __restrict__ wskip, const float* __restrict__ bskip,
                        const float* __restrict__ wc, const float* __restrict__ bc) {
    int tid = blockIdx.x * blockDim.x + threadIdx.x;
    if (tid < 64 * 64) {
        int k2 = tid >> 6, o = tid & 63;
        float lo = 0.f, hi = 0.f;
        for (int p = 0; p < HD; ++p) {
            float w = wc[p * OUTD + o];
            lo += wskip[(2 * k2) * HD + p] * w;
            hi += wskip[(2 * k2 + 1) * HD + p] * w;
        }
        g_wscp[tid] = pack_pair(lo, hi);
    } else if (tid < 64 * 64 + OUTD) {
        int o = tid - 4096;
        float s = bc[o];
        for (int p = 0; p < HD; ++p) s += bskip[p] * wc[p * OUTD + o];
        g_bsc[o] = s;
    }
}

// ---------------- pair all static weights in one kernel ----------------
__global__ void k_pair_all(const float* __restrict__ w1, const float* __restrict__ w2,
                           const float* __restrict__ wih, const float* __restrict__ whh,
                           const float* __restrict__ wq, const float* __restrict__ wk,
                           const float* __restrict__ wv, const float* __restrict__ wc) {
    int i = blockIdx.x * blockDim.x + threadIdx.x;
    if (i < 17408) {                                    // w1: [272][128]
        int k2 = i >> 7, c = i & 127;
        g_w1p[i] = pack_pair(w1[(2 * k2) * 128 + c], w1[(2 * k2 + 1) * 128 + c]);
        return;
    }
    i -= 17408;
    if (i < 8192) {                                     // w2: [128][128]
        int k2 = i >> 7, c = i & 127;
        g_w2p[i] = pack_pair(w2[(2 * k2) * 128 + c], w2[(2 * k2 + 1) * 128 + c]);
        return;
    }
    i -= 8192;
    if (i < 24576) {                                    // wih: [384][128], W[k][c]=wih[c][k]
        int k2 = i / 384, c = i % 384;
        g_wip[i] = pack_pair(wih[c * 128 + 2 * k2], wih[c * 128 + 2 * k2 + 1]);
        return;
    }
    i -= 24576;
    if (i < 24576) {
        int k2 = i / 384, c = i % 384;
        g_whp[i] = pack_pair(whh[c * 128 + 2 * k2], whh[c * 128 + 2 * k2 + 1]);
        return;
    }
    i -= 24576;
    if (i < 16384) {                                    // wq: [128][256]
        int k2 = i >> 8, c = i & 255;
        g_qkvp[k2 * 768 + c] = pack_pair(wq[2 * k2 * 256 + c], wq[(2 * k2 + 1) * 256 + c]);
        return;
    }
    i -= 16384;
    if (i < 16384) {
        int k2 = i >> 8, c = i & 255;
        g_qkvp[k2 * 768 + 256 + c] = pack_pair(wk[2 * k2 * 256 + c], wk[(2 * k2 + 1) * 256 + c]);
        return;
    }
    i -= 16384;
    if (i < 16384) {
        int k2 = i >> 8, c = i & 255;
        g_qkvp[k2 * 768 + 512 + c] = pack_pair(wv[2 * k2 * 256 + c], wv[(2 * k2 + 1) * 256 + c]);
        return;
    }
    i -= 16384;
    if (i < 8192) {                                     // wc: [256][64]
        int k2 = i >> 6, c = i & 63;
        g_wcp[i] = pack_pair(wc[2 * k2 * OUTD + c], wc[(2 * k2 + 1) * OUTD + c]);
    }
}

// ---------------- winner edge per dst node ----------------
__global__ void k_winner(const void* __restrict__ ei) {
    int e = blockIdx.x * blockDim.x + threadIdx.x;
    if (e < EE) {
        int dst = ld_idx(ei, (size_t)EE + e);
        atomicMax(&g_winner[dst], e);
    }
}

// ---------------- fused message MLP + GRU (16 nodes/block, K-paired fma2) ----------------
__global__ __launch_bounds__(256) void k_node(
    const void* __restrict__ ei, const float* __restrict__ edge_attr,
    const float* __restrict__ memory,
    const float* __restrict__ b1, const float* __restrict__ b2,
    const float* __restrict__ bih, const float* __restrict__ bhh)
{
    __shared__ __align__(16) float X[16 * XDIM];
    __shared__ __align__(16) float H1v[16 * DD];
    __shared__ __align__(16) float MS[16 * DD];
    __shared__ int s_src[16], s_e[16];

    const int t = threadIdx.x;
    const int nb = blockIdx.x * 16;

    if (t < 16) {
        int w = g_winner[nb + t];
        s_e[t] = w;
        s_src[t] = (w >= 0) ? ld_idx(ei, w) : -1;
    }
    __syncthreads();

    for (int idx = t; idx < 16 * XDIM; idx += 256) {
        int m = idx / XDIM;
        int k = idx - m * XDIM;
        float v;
        if (k < DD) {
            int s = s_src[m];
            v = (s >= 0) ? memory[(size_t)s * DD + k] : 0.f;
        } else if (k < 2 * DD) {
            v = memory[(size_t)(nb + m) * DD + (k - DD)];
        } else {
            int e = s_e[m];
            v = (e >= 0) ? edge_attr[(size_t)e * EFD + (k - 2 * DD)] : 0.f;
        }
        X[idx] = v;
    }
    __syncthreads();

    const int jq = t & 31, mg = t >> 5;
    const int j0 = jq * 4, m0 = mg * 2;

    // ---- phase B: h1 = relu(X @ w1 + b1), K split across f32x2 lanes ----
    {
        u64 acc[2][4] = {{0,0,0,0},{0,0,0,0}};
        #pragma unroll 2
        for (int k2 = 0; k2 < 136; ++k2) {
            const u64* wp = g_w1p + k2 * 128 + j0;
            ulonglong2 wa = *(const ulonglong2*)(wp);
            ulonglong2 wb = *(const ulonglong2*)(wp + 2);
            #pragma unroll
            for (int i = 0; i < 2; ++i) {
                u64 x2 = ldp(&X[(m0 + i) * XDIM + 2 * k2]);
                fma2(acc[i][0], x2, wa.x); fma2(acc[i][1], x2, wa.y);
                fma2(acc[i][2], x2, wb.x); fma2(acc[i][3], x2, wb.y);
            }
        }
        float b[4]; *(float4*)b = ld4(b1 + j0);
        #pragma unroll
        for (int i = 0; i < 2; ++i) {
            float o[4];
            #pragma unroll
            for (int c = 0; c < 4; ++c) {
                float2 p = unpack2(acc[i][c]);
                o[c] = fmaxf(p.x + p.y + b[c], 0.f);
            }
            *(float4*)&H1v[(m0 + i) * DD + j0] = *(float4*)o;
        }
    }
    __syncthreads();

    // ---- phase C: msg = h1 @ w2 + b2 ----
    {
        u64 acc[2][4] = {{0,0,0,0},{0,0,0,0}};
        #pragma unroll 2
        for (int k2 = 0; k2 < 64; ++k2) {
            const u64* wp = g_w2p + k2 * 128 + j0;
            ulonglong2 wa = *(const ulonglong2*)(wp);
            ulonglong2 wb = *(const ulonglong2*)(wp + 2);
            #pragma unroll
            for (int i = 0; i < 2; ++i) {
                u64 x2 = ldp(&H1v[(m0 + i) * DD + 2 * k2]);
                fma2(acc[i][0], x2, wa.x); fma2(acc[i][1], x2, wa.y);
                fma2(acc[i][2], x2, wb.x); fma2(acc[i][3], x2, wb.y);
            }
        }
        float b[4]; *(float4*)b = ld4(b2 + j0);
        #pragma unroll
        for (int i = 0; i < 2; ++i) {
            float o[4];
            #pragma unroll
            for (int c = 0; c < 4; ++c) {
                float2 p = unpack2(acc[i][c]);
                o[c] = p.x + p.y + b[c];
            }
            *(float4*)&MS[(m0 + i) * DD + j0] = *(float4*)o;
        }
    }
    __syncthreads();

    // ---- phase D: GRU gates ----
    {
        u64 aR[2][4]  = {{0,0,0,0},{0,0,0,0}};
        u64 aZ[2][4]  = {{0,0,0,0},{0,0,0,0}};
        u64 aIN[2][4] = {{0,0,0,0},{0,0,0,0}};
        u64 aHN[2][4] = {{0,0,0,0},{0,0,0,0}};

        #pragma unroll 1
        for (int k2 = 0; k2 < 64; ++k2) {
            const u64* wi = g_wip + k2 * 384;
            const u64* wh = g_whp + k2 * 384;
            ulonglong2 wir0 = *(const ulonglong2*)(wi + j0);
            ulonglong2 wir1 = *(const ulonglong2*)(wi + j0 + 2);
            ulonglong2 wiz0 = *(const ulonglong2*)(wi + 128 + j0);
            ulonglong2 wiz1 = *(const ulonglong2*)(wi + 128 + j0 + 2);
            ulonglong2 win0 = *(const ulonglong2*)(wi + 256 + j0);
            ulonglong2 win1 = *(const ulonglong2*)(wi + 256 + j0 + 2);
            ulonglong2 whr0 = *(const ulonglong2*)(wh + j0);
            ulonglong2 whr1 = *(const ulonglong2*)(wh + j0 + 2);
            ulonglong2 whz0 = *(const ulonglong2*)(wh + 128 + j0);
            ulonglong2 whz1 = *(const ulonglong2*)(wh + 128 + j0 + 2);
            ulonglong2 whn0 = *(const ulonglong2*)(wh + 256 + j0);
            ulonglong2 whn1 = *(const ulonglong2*)(wh + 256 + j0 + 2);
            #pragma unroll
            for (int i = 0; i < 2; ++i) {
                u64 xm = ldp(&MS[(m0 + i) * DD + 2 * k2]);
                u64 xd = ldp(&X[(m0 + i) * XDIM + DD + 2 * k2]);
                fma2(aR[i][0], xm, wir0.x); fma2(aR[i][1], xm, wir0.y);
                fma2(aR[i][2], xm, wir1.x); fma2(aR[i][3], xm, wir1.y);
                fma2(aR[i][0], xd, whr0.x); fma2(aR[i][1], xd, whr0.y);
                fma2(aR[i][2], xd, whr1.x); fma2(aR[i][3], xd, whr1.y);
                fma2(aZ[i][0], xm, wiz0.x); fma2(aZ[i][1], xm, wiz0.y);
                fma2(aZ[i][2], xm, wiz1.x); fma2(aZ[i][3], xm, wiz1.y);
                fma2(aZ[i][0], xd, whz0.x); fma2(aZ[i][1], xd, whz0.y);
                fma2(aZ[i][2], xd, whz1.x); fma2(aZ[i][3], xd, whz1.y);
                fma2(aIN[i][0], xm, win0.x); fma2(aIN[i][1], xm, win0.y);
                fma2(aIN[i][2], xm, win1.x); fma2(aIN[i][3], xm, win1.y);
                fma2(aHN[i][0], xd, whn0.x); fma2(aHN[i][1], xd, whn0.y);
                fma2(aHN[i][2], xd, whn1.x); fma2(aHN[i][3], xd, whn1.y);
            }
        }

        float bir[4], biz[4], bin_[4], bhr[4], bhz[4], bhn[4];
        *(float4*)bir  = ld4(bih + j0);
        *(float4*)biz  = ld4(bih + DD + j0);
        *(float4*)bin_ = ld4(bih + 2 * DD + j0);
        *(float4*)bhr  = ld4(bhh + j0);
        *(float4*)bhz  = ld4(bhh + DD + j0);
        *(float4*)bhn  = ld4(bhh + 2 * DD + j0);

        #pragma unroll
        for (int i = 0; i < 2; ++i) {
            bool win_ = (s_e[m0 + i] >= 0);
            float o[4];
            #pragma unroll
            for (int c = 0; c < 4; ++c) {
                float2 pr = unpack2(aR[i][c]);
                float2 pz = unpack2(aZ[i][c]);
                float2 pi = unpack2(aIN[i][c]);
                float2 ph = unpack2(aHN[i][c]);
                float xd = X[(m0 + i) * XDIM + DD + j0 + c];
                float r = sigm(pr.x + pr.y + bir[c] + bhr[c]);
                float z = sigm(pz.x + pz.y + biz[c] + bhz[c]);
                float nn = tanh_f(pi.x + pi.y + bin_[c] + r * (ph.x + ph.y + bhn[c]));
                o[c] = win_ ? ((1.f - z) * nn + z * xd) : xd;
            }
            *(float4*)&g_node_mem[(size_t)(nb + m0 + i) * DD + j0] = *(float4*)o;
        }
    }
}

// ---------------- fused q/k/v GEMM: [64 nodes x 128 cols]/block over 768 cols ----------------
__global__ __launch_bounds__(256) void k_qkv(const float* __restrict__ bq,
                                             const float* __restrict__ bk,
                                             const float* __restrict__ bv) {
    __shared__ __align__(16) float Xs[64 * DD];  // 32 KB
    const int t = threadIdx.x;
    const int mb = blockIdx.x * 64;
    const int pb = blockIdx.y * 128;             // 0,128,...,640

    for (int idx = t; idx < 64 * DD; idx += 256) {
        int m = idx >> 7, k = idx & 127;
        Xs[idx] = (mb + m < NN) ? g_node_mem[(size_t)(mb + m) * DD + k] : 0.f;
    }
    __syncthreads();

    const int cq = t & 15, mq = t >> 4;
    const int c0 = cq * 8, m0 = mq * 4;

    u64 acc[4][8];
    #pragma unroll
    for (int i = 0; i < 4; ++i)
        #pragma unroll
        for (int c = 0; c < 8; ++c) acc[i][c] = 0ull;

    #pragma unroll 2
    for (int k2 = 0; k2 < 64; ++k2) {
        const u64* wp = g_qkvp + k2 * 768 + pb + c0;
        ulonglong2 w0 = *(const ulonglong2*)(wp);
        ulonglong2 w1 = *(const ulonglong2*)(wp + 2);
        ulonglong2 w2 = *(const ulonglong2*)(wp + 4);
        ulonglong2 w3 = *(const ulonglong2*)(wp + 6);
        #pragma unroll
        for (int i = 0; i < 4; ++i) {
            u64 x2 = ldp(&Xs[(m0 + i) * DD + 2 * k2]);
            fma2(acc[i][0], x2, w0.x); fma2(acc[i][1], x2, w0.y);
            fma2(acc[i][2], x2, w1.x); fma2(acc[i][3], x2, w1.y);
            fma2(acc[i][4], x2, w2.x); fma2(acc[i][5], x2, w2.y);
            fma2(acc[i][6], x2, w3.x); fma2(acc[i][7], x2, w3.y);
        }
    }

    int sec = pb >> 8;                      // 0=q, 1=k, 2=v
    int local = (pb & 255) + c0;
    float* Y = (sec == 0) ? g_q : (sec == 1) ? g_k : g_v;
    const float* bias = (sec == 0) ? bq : (sec == 1) ? bk : bv;
    float b[8];
    *(float4*)b       = ld4(bias + local);
    *(float4*)(b + 4) = ld4(bias + local + 4);

    #pragma unroll
    for (int i = 0; i < 4; ++i) {
        if (mb + m0 + i < NN) {
            float o[8];
            #pragma unroll
            for (int c = 0; c < 8; ++c) {
                float2 p = unpack2(acc[i][c]);
                o[c] = p.x + p.y + b[c];
            }
            float* dst = Y + (size_t)(mb + m0 + i) * HD + local;
            *(float4*)dst       = *(float4*)o;
            *(float4*)(dst + 4) = *(float4*)(o + 4);
        }
    }
}

// ---------------- attention pass A: exp(logits) + segment sum (warp per edge) ----------------
__global__ void k_att_a(const void* __restrict__ ei) {
    int w = (blockIdx.x * blockDim.x + threadIdx.x) >> 5;
    int lane = threadIdx.x & 31;
    if (w >= EE) return;
    int src = ld_idx(ei, w);
    int dst = ld_idx(ei, (size_t)EE + w);
    const float4* q4 = (const float4*)(g_q + (size_t)dst * HD);
    const float4* k4 = (const float4*)(g_k + (size_t)src * HD);
    float4 qa = q4[lane],      ka = k4[lane];
    float4 qb = q4[lane + 32], kb = k4[lane + 32];
    float p0 = qa.x * ka.x + qa.y * ka.y + qa.z * ka.z + qa.w * ka.w;
    float p1 = qb.x * kb.x + qb.y * kb.y + qb.z * kb.z + qb.w * kb.w;
    #pragma unroll
    for (int o = 16; o; o >>= 1) {
        p0 += __shfl_xor_sync(0xffffffffu, p0, o);
        p1 += __shfl_xor_sync(0xffffffffu, p1, o);
    }
    if (lane == 0) {
        const float sc = 0.08838834764831845f;  // 1/sqrt(128)
        float e0 = __expf(p0 * sc), e1 = __expf(p1 * sc);
        g_logit[(size_t)w * 2]     = e0;
        g_logit[(size_t)w * 2 + 1] = e1;
        atomicAdd(&g_sum[dst * 2],     e0);
        atomicAdd(&g_sum[dst * 2 + 1], e1);
    }
}

// ---------------- attention pass C: agg += alpha * v[src] (warp per edge, vector REDs) ----------------
__global__ void k_att_c(const void* __restrict__ ei) {
    int w = (blockIdx.x * blockDim.x + threadIdx.x) >> 5;
    int lane = threadIdx.x & 31;
    if (w >= EE) return;
    int src = ld_idx(ei, w);
    int dst = ld_idx(ei, (size_t)EE + w);
    float a0 = g_logit[(size_t)w * 2]     / (g_sum[dst * 2]     + 1e-16f);
    float a1 = g_logit[(size_t)w * 2 + 1] / (g_sum[dst * 2 + 1] + 1e-16f);
    const float4* v4 = (const float4*)(g_v + (size_t)src * HD);
    float4 va = v4[lane];
    float4 vb = v4[lane + 32];
    float* ag = g_agg + (size_t)dst * HD;
    red4(ag + lane * 4,      va.x * a0, va.y * a0, va.z * a0, va.w * a0);
    red4(ag + DD + lane * 4, vb.x * a1, vb.y * a1, vb.z * a1, vb.w * a1);
}

// ---------------- final: out = agg @ wc + node_mem @ wsc + bsc ----------------
__global__ __launch_bounds__(256) void k_final(float* __restrict__ out) {
    __shared__ __align__(16) float As[32 * HD];  // 32 KB
    const int t = threadIdx.x;
    const int nb = blockIdx.x * 32;
    const int cq = t & 15, mq = t >> 4;
    const int c0 = cq * 4, m0 = mq * 2;

    u64 acc[2][4] = {{0,0,0,0},{0,0,0,0}};

    // stage 1: agg @ wc (paired over K=256)
    for (int idx = t; idx < 32 * HD; idx += 256)
        As[idx] = g_agg[(size_t)nb * HD + idx];
    __syncthreads();
    #pragma unroll 2
    for (int k2 = 0; k2 < 128; ++k2) {
        const u64* wp = g_wcp + k2 * OUTD + c0;
        ulonglong2 wa = *(const ulonglong2*)(wp);
        ulonglong2 wb = *(const ulonglong2*)(wp + 2);
        #pragma unroll
        for (int i = 0; i < 2; ++i) {
            u64 x2 = ldp(&As[(m0 + i) * HD + 2 * k2]);
            fma2(acc[i][0], x2, wa.x); fma2(acc[i][1], x2, wa.y);
            fma2(acc[i][2], x2, wb.x); fma2(acc[i][3], x2, wb.y);
        }
    }
    __syncthreads();

    // stage 2: node_mem @ wsc (paired over K=128)
    for (int idx = t; idx < 32 * DD; idx += 256)
        As[idx] = g_node_mem[(size_t)nb * DD + idx];
    __syncthreads();
    #pragma unroll 2
    for (int k2 = 0; k2 < 64; ++k2) {
        const u64* wp = g_wscp + k2 * OUTD + c0;
        ulonglong2 wa = *(const ulonglong2*)(wp);
        ulonglong2 wb = *(const ulonglong2*)(wp + 2);
        #pragma unroll
        for (int i = 0; i < 2; ++i) {
            u64 x2 = ldp(&As[(m0 + i) * DD + 2 * k2]);
            fma2(acc[i][0], x2, wa.x); fma2(acc[i][1], x2, wa.y);
            fma2(acc[i][2], x2, wb.x); fma2(acc[i][3], x2, wb.y);
        }
    }

    float b[4]; *(float4*)b = ld4(g_bsc + c0);
    #pragma unroll
    for (int i = 0; i < 2; ++i) {
        float o[4];
        #pragma unroll
        for (int c = 0; c < 4; ++c) {
            float2 p = unpack2(acc[i][c]);
            o[c] = p.x + p.y + b[c];
        }
        *(float4*)&out[(size_t)(nb + m0 + i) * OUTD + c0] = *(float4*)o;
    }
}

// ---------------- launch ----------------
extern "C" void kernel_launch(void* const* d_in, const int* in_sizes, int n_in,
                              void* d_out, int out_size) {
    const void* ei  = d_in[0];
    const float* edge_attr = (const float*)d_in[1];
    // d_in[2] = edge_time (unused)
    const float* memory = (const float*)d_in[3];
    const float* w1 = (const float*)d_in[4];
    const float* b1 = (const float*)d_in[5];
    const float* w2 = (const float*)d_in[6];
    const float* b2 = (const float*)d_in[7];
    const float* gwih = (const float*)d_in[8];
    const float* gwhh = (const float*)d_in[9];
    const float* gbih = (const float*)d_in[10];
    const float* gbhh = (const float*)d_in[11];
    const float* wq = (const float*)d_in[12];
    const float* bq = (const float*)d_in[13];
    const float* wk = (const float*)d_in[14];
    const float* bk = (const float*)d_in[15];
    const float* wv = (const float*)d_in[16];
    const float* bv = (const float*)d_in[17];
    const float* wskip = (const float*)d_in[18];
    const float* bskip = (const float*)d_in[19];
    const float* wc = (const float*)d_in[20];
    const float* bc = (const float*)d_in[21];
    float* out = (float*)d_out;

    k_detect<<<1, 256>>>(ei);
    k_init<<<(NN * HD + 255) / 256, 256>>>();
    k_fusew<<<17, 256>>>(wskip, bskip, wc, bc);
    k_pair_all<<<516, 256>>>(w1, w2, gwih, gwhh, wq, wk, wv, wc);
    k_winner<<<(EE + 255) / 256, 256>>>(ei);
    k_node<<<NN / 16, 256>>>(ei, edge_attr, memory, b1, b2, gbih, gbhh);   // ncu -s 5 lands here

    dim3 gq((NN + 63) / 64, 6);
    k_qkv<<<gq, 256>>>(bq, bk, bv);

    k_att_a<<<EE / 8, 256>>>(ei);
    k_att_c<<<EE / 8, 256>>>(ei);

    k_final<<<NN / 32, 256>>>(out);
}

// round 16
// speedup vs baseline: 1.7005x; 1.7005x over previous
#include <cuda_runtime.h>
#include <math.h>

#define NN   100000
#define EE   500000
#define DD   128
#define EFD  16
#define XDIM 272        // 2*DD + EFD
#define HH   2
#define HD   256        // HH * DD
#define OUTD 64

typedef unsigned long long u64;

// ---------------- scratch (device globals; no allocation allowed) ----------------
__device__ int      g_is64;                     // edge_index dtype flag (1 = int64, 0 = int32)
__device__ int      g_winner[NN];
__device__ __align__(16) float g_node_mem[(size_t)NN * DD];
__device__ __align__(16) float g_q[(size_t)NN * HD];
__device__ __align__(16) float g_k[(size_t)NN * HD];
__device__ __align__(16) float g_v[(size_t)NN * HD];
__device__ __align__(16) float g_logit[(size_t)EE * HH];   // exp(logit)
__device__ float    g_sum[NN * HH];
__device__ __align__(16) float g_agg[(size_t)NN * HD];
__device__ __align__(16) float g_wihT[DD * 3 * DD];        // [128][384]
__device__ __align__(16) float g_whhT[DD * 3 * DD];
__device__ __align__(16) float g_wsc[DD * OUTD];           // wskip @ wc
__device__ __align__(16) float g_bsc[OUTD];                // bskip @ wc + bc

// edge_index accessor: dtype decided at runtime by k_detect (deterministic per input)
__device__ __forceinline__ int ld_idx(const void* ei, size_t i) {
    if (g_is64) return (int)((const long long*)ei)[i];
    return ((const int*)ei)[i];
}

__device__ __forceinline__ float4 ld4(const float* p) {
    return *reinterpret_cast<const float4*>(p);
}

// ---- packed f32x2 helpers (FFMA2: PTX-only pattern, 2x fp32 fma throughput) ----
// broadcast-pack form: accumulators stay compact (register-pressure-safe; the
// K-paired variant with 32 u64 accumulators spilled and regressed 69%)
__device__ __forceinline__ u64 pack2(float x) {
    u64 r; asm("mov.b64 %0,{%1,%1};" : "=l"(r) : "f"(x)); return r;
}
__device__ __forceinline__ void fma2(u64& a, u64 x, u64 w) {
    asm("fma.rn.f32x2 %0,%1,%2,%0;" : "+l"(a) : "l"(x), "l"(w));
}
__device__ __forceinline__ float2 unpack2(u64 a) {
    float2 f; asm("mov.b64 {%0,%1},%2;" : "=f"(f.x), "=f"(f.y) : "l"(a)); return f;
}
__device__ __forceinline__ ulonglong2 ldw2(const float* p) {
    return *reinterpret_cast<const ulonglong2*>(p);
}
// vector reduction: 4 floats in one RED op (sm_90+)
__device__ __forceinline__ void red4(float* addr, float a, float b, float c, float d) {
    asm volatile("red.global.add.v4.f32 [%0], {%1,%2,%3,%4};"
                 :: "l"(addr), "f"(a), "f"(b), "f"(c), "f"(d) : "memory");
}
// fast transcendentals (abs err ~1e-7 at these magnitudes; validated in round 10)
__device__ __forceinline__ float sigm(float x) { return __fdividef(1.f, 1.f + __expf(-x)); }
__device__ __forceinline__ float tanh_f(float x) { return __fdividef(2.f, 1.f + __expf(-2.f * x)) - 1.f; }

// ---------------- dtype detect (standalone: the exact form proven in rounds 6/8/10) ----------------
__global__ void k_detect(const void* ei) {
    __shared__ int bad;
    int t = threadIdx.x;
    if (t == 0) bad = 0;
    __syncthreads();
    long long v = ((const long long*)ei)[t];   // first 2KB, in bounds either way
    if (v < 0 || v >= NN) atomicExch(&bad, 1);
    __syncthreads();
    if (t == 0) g_is64 = bad ? 0 : 1;
}

// ---------------- init: zero agg, winner=-1, softmax sums ----------------
__global__ void k_init() {
    size_t i = (size_t)blockIdx.x * blockDim.x + threadIdx.x;
    if (i < (size_t)NN * HD) g_agg[i] = 0.f;
    if (i < NN) g_winner[i] = -1;
    if (i < (size_t)NN * HH) g_sum[i] = 0.f;
}

// ---------------- winner edge per dst + GRU weight transpose (fused; both flat loops) ----------------
__global__ void k_winner_t(const void* __restrict__ ei,
                           const float* __restrict__ wih, const float* __restrict__ whh) {
    int e = blockIdx.x * blockDim.x + threadIdx.x;
    const int T = DD * 3 * DD; // 49152
    if (e < T) {
        int k = e / (3 * DD), j = e % (3 * DD);
        g_wihT[e] = wih[j * DD + k];
        g_whhT[e] = whh[j * DD + k];
    }
    if (e < EE) {
        int dst = ld_idx(ei, (size_t)EE + e);
        atomicMax(&g_winner[dst], e);
    }
}

// ---------------- fused message MLP + GRU memory update (16 nodes / block) ----------------
__global__ __launch_bounds__(256) void k_node(
    const void* __restrict__ ei, const float* __restrict__ edge_attr,
    const float* __restrict__ memory,
    const float* __restrict__ w1, const float* __restrict__ b1,
    const float* __restrict__ w2, const float* __restrict__ b2,
    const float* __restrict__ bih, const float* __restrict__ bhh)
{
    __shared__ __align__(16) float X[16 * XDIM];    // [16][272]  (src | dst | attr)
    __shared__ __align__(16) float H1v[16 * DD];    // [16][128]
    __shared__ __align__(16) float MS[16 * DD];     // [16][128]
    __shared__ int s_src[16], s_e[16];

    const int t = threadIdx.x;
    const int nb = blockIdx.x * 16;

    if (t < 16) {
        int w = g_winner[nb + t];
        s_e[t] = w;
        s_src[t] = (w >= 0) ? ld_idx(ei, w) : -1;
    }
    __syncthreads();

    // gather inputs
    for (int idx = t; idx < 16 * XDIM; idx += 256) {
        int m = idx / XDIM;
        int k = idx - m * XDIM;
        float v;
        if (k < DD) {
            int s = s_src[m];
            v = (s >= 0) ? memory[(size_t)s * DD + k] : 0.f;
        } else if (k < 2 * DD) {
            v = memory[(size_t)(nb + m) * DD + (k - DD)];
        } else {
            int e = s_e[m];
            v = (e >= 0) ? edge_attr[(size_t)e * EFD + (k - 2 * DD)] : 0.f;
        }
        X[idx] = v;
    }
    __syncthreads();

    const int jq = t & 31, mg = t >> 5;
    const int j0 = jq * 4, m0 = mg * 2;

    // ---- phase B: h1 = relu(X @ w1 + b1) ----
    {
        u64 acc[2][2] = {{0ull, 0ull}, {0ull, 0ull}};
        #pragma unroll 4
        for (int k = 0; k < XDIM; ++k) {
            ulonglong2 wv = ldw2(w1 + k * DD + j0);
            #pragma unroll
            for (int i = 0; i < 2; ++i) {
                u64 x2 = pack2(X[(m0 + i) * XDIM + k]);
                fma2(acc[i][0], x2, wv.x);
                fma2(acc[i][1], x2, wv.y);
            }
        }
        float b[4]; *(float4*)b = ld4(b1 + j0);
        #pragma unroll
        for (int i = 0; i < 2; ++i) {
            float2 lo = unpack2(acc[i][0]), hi = unpack2(acc[i][1]);
            float o[4] = { fmaxf(lo.x + b[0], 0.f), fmaxf(lo.y + b[1], 0.f),
                           fmaxf(hi.x + b[2], 0.f), fmaxf(hi.y + b[3], 0.f) };
            *(float4*)&H1v[(m0 + i) * DD + j0] = *(float4*)o;
        }
    }
    __syncthreads();

    // ---- phase C: msg = h1 @ w2 + b2 ----
    {
        u64 acc[2][2] = {{0ull, 0ull}, {0ull, 0ull}};
        #pragma unroll 4
        for (int k = 0; k < DD; ++k) {
            ulonglong2 wv = ldw2(w2 + k * DD + j0);
            #pragma unroll
            for (int i = 0; i < 2; ++i) {
                u64 x2 = pack2(H1v[(m0 + i) * DD + k]);
                fma2(acc[i][0], x2, wv.x);
                fma2(acc[i][1], x2, wv.y);
            }
        }
        float b[4]; *(float4*)b = ld4(b2 + j0);
        #pragma unroll
        for (int i = 0; i < 2; ++i) {
            float2 lo = unpack2(acc[i][0]), hi = unpack2(acc[i][1]);
            float o[4] = { lo.x + b[0], lo.y + b[1], hi.x + b[2], hi.y + b[3] };
            *(float4*)&MS[(m0 + i) * DD + j0] = *(float4*)o;
        }
    }
    __syncthreads();

    // ---- phase D: GRU gates ----
    {
        u64 aR[2][2]  = {{0ull,0ull},{0ull,0ull}};
        u64 aZ[2][2]  = {{0ull,0ull},{0ull,0ull}};
        u64 aIN[2][2] = {{0ull,0ull},{0ull,0ull}};
        u64 aHN[2][2] = {{0ull,0ull},{0ull,0ull}};

        #pragma unroll 2
        for (int k = 0; k < DD; ++k) {
            const float* wi = g_wihT + k * (3 * DD);
            const float* wh = g_whhT + k * (3 * DD);
            ulonglong2 wir = ldw2(wi + j0);
            ulonglong2 wiz = ldw2(wi + DD + j0);
            ulonglong2 win = ldw2(wi + 2 * DD + j0);
            ulonglong2 whr = ldw2(wh + j0);
            ulonglong2 whz = ldw2(wh + DD + j0);
            ulonglong2 whn = ldw2(wh + 2 * DD + j0);
            #pragma unroll
            for (int i = 0; i < 2; ++i) {
                u64 xm = pack2(MS[(m0 + i) * DD + k]);
                u64 xd = pack2(X[(m0 + i) * XDIM + DD + k]);
                fma2(aR[i][0],  xm, wir.x); fma2(aR[i][1],  xm, wir.y);
                fma2(aR[i][0],  xd, whr.x); fma2(aR[i][1],  xd, whr.y);
                fma2(aZ[i][0],  xm, wiz.x); fma2(aZ[i][1],  xm, wiz.y);
                fma2(aZ[i][0],  xd, whz.x); fma2(aZ[i][1],  xd, whz.y);
                fma2(aIN[i][0], xm, win.x); fma2(aIN[i][1], xm, win.y);
                fma2(aHN[i][0], xd, whn.x); fma2(aHN[i][1], xd, whn.y);
            }
        }

        float bir[4], biz[4], bin_[4], bhr[4], bhz[4], bhn[4];
        *(float4*)bir  = ld4(bih + j0);
        *(float4*)biz  = ld4(bih + DD + j0);
        *(float4*)bin_ = ld4(bih + 2 * DD + j0);
        *(float4*)bhr  = ld4(bhh + j0);
        *(float4*)bhz  = ld4(bhh + DD + j0);
        *(float4*)bhn  = ld4(bhh + 2 * DD + j0);

        #pragma unroll
        for (int i = 0; i < 2; ++i) {
            bool win_ = (s_e[m0 + i] >= 0);
            float fr[4], fz[4], fin[4], fhn[4];
            float2 v;
            v = unpack2(aR[i][0]);  fr[0]=v.x;  fr[1]=v.y;  v = unpack2(aR[i][1]);  fr[2]=v.x;  fr[3]=v.y;
            v = unpack2(aZ[i][0]);  fz[0]=v.x;  fz[1]=v.y;  v = unpack2(aZ[i][1]);  fz[2]=v.x;  fz[3]=v.y;
            v = unpack2(aIN[i][0]); fin[0]=v.x; fin[1]=v.y; v = unpack2(aIN[i][1]); fin[2]=v.x; fin[3]=v.y;
            v = unpack2(aHN[i][0]); fhn[0]=v.x; fhn[1]=v.y; v = unpack2(aHN[i][1]); fhn[2]=v.x; fhn[3]=v.y;
            float o[4];
            #pragma unroll
            for (int c = 0; c < 4; ++c) {
                float xd = X[(m0 + i) * XDIM + DD + j0 + c];
                float r = sigm(fr[c] + bir[c] + bhr[c]);
                float z = sigm(fz[c] + biz[c] + bhz[c]);
                float nn = tanh_f(fin[c] + bin_[c] + r * (fhn[c] + bhn[c]));
                o[c] = win_ ? ((1.f - z) * nn + z * xd) : xd;
            }
            *(float4*)&g_node_mem[(size_t)(nb + m0 + i) * DD + j0] = *(float4*)o;
        }
    }
}

// ---------------- q/k/v GEMM: Y = node_mem @ W + b, Y selected by sel ----------------
__global__ __launch_bounds__(256) void k_gemm(const float* __restrict__ W,
                                              const float* __restrict__ bias,
                                              int sel) {
    float* Y = (sel == 0) ? g_q : (sel == 1) ? g_k : g_v;
    const int P = HD;
    __shared__ __align__(16) float Xs[64 * DD];  // 32 KB
    const int t = threadIdx.x;
    const int mb = blockIdx.x * 64;
    const int pb = blockIdx.y * 64;

    for (int idx = t; idx < 64 * DD; idx += 256) {
        int m = idx >> 7, k = idx & 127;
        Xs[idx] = (mb + m < NN) ? g_node_mem[(size_t)(mb + m) * DD + k] : 0.f;
    }
    __syncthreads();

    const int pq = t & 15, mq = t >> 4;
    const int p0 = pq * 4, m0 = mq * 4;
    u64 acc[4][2] = {{0ull,0ull},{0ull,0ull},{0ull,0ull},{0ull,0ull}};

    #pragma unroll 4
    for (int k = 0; k < DD; ++k) {
        ulonglong2 wv = ldw2(W + (size_t)k * P + pb + p0);
        #pragma unroll
        for (int i = 0; i < 4; ++i) {
            u64 x2 = pack2(Xs[(m0 + i) * DD + k]);
            fma2(acc[i][0], x2, wv.x);
            fma2(acc[i][1], x2, wv.y);
        }
    }
    float b[4]; *(float4*)b = ld4(bias + pb + p0);
    #pragma unroll
    for (int i = 0; i < 4; ++i) {
        if (mb + m0 + i < NN) {
            float2 lo = unpack2(acc[i][0]), hi = unpack2(acc[i][1]);
            float o[4] = { lo.x + b[0], lo.y + b[1], hi.x + b[2], hi.y + b[3] };
            *(float4*)&Y[(size_t)(mb + m0 + i) * P + pb + p0] = *(float4*)o;
        }
    }
}

// ---------------- attention pass A: exp(logits) + segment sum (warp per edge) ----------------
// max-subtraction dropped: |logit| << 1 here, exp cannot overflow; alpha unchanged algebraically
__global__ void k_att_a(const void* __restrict__ ei) {
    int w = (blockIdx.x * blockDim.x + threadIdx.x) >> 5;
    int lane = threadIdx.x & 31;
    if (w >= EE) return;
    int src = ld_idx(ei, w);
    int dst = ld_idx(ei, (size_t)EE + w);
    const float4* q4 = (const float4*)(g_q + (size_t)dst * HD);
    const float4* k4 = (const float4*)(g_k + (size_t)src * HD);
    float4 qa = q4[lane],      ka = k4[lane];
    float4 qb = q4[lane + 32], kb = k4[lane + 32];
    float p0 = qa.x * ka.x + qa.y * ka.y + qa.z * ka.z + qa.w * ka.w;
    float p1 = qb.x * kb.x + qb.y * kb.y + qb.z * kb.z + qb.w * kb.w;
    #pragma unroll
    for (int o = 16; o; o >>= 1) {
        p0 += __shfl_xor_sync(0xffffffffu, p0, o);
        p1 += __shfl_xor_sync(0xffffffffu, p1, o);
    }
    if (lane == 0) {
        const float sc = 0.08838834764831845f;  // 1/sqrt(128)
        float e0 = __expf(p0 * sc), e1 = __expf(p1 * sc);
        g_logit[(size_t)w * 2]     = e0;
        g_logit[(size_t)w * 2 + 1] = e1;
        atomicAdd(&g_sum[dst * 2],     e0);
        atomicAdd(&g_sum[dst * 2 + 1], e1);
    }
}

// ---------------- attention pass C: agg += alpha * v[src] (warp per edge, vector REDs) ----------------
__global__ void k_att_c(const void* __restrict__ ei) {
    int w = (blockIdx.x * blockDim.x + threadIdx.x) >> 5;
    int lane = threadIdx.x & 31;
    if (w >= EE) return;
    int src = ld_idx(ei, w);
    int dst = ld_idx(ei, (size_t)EE + w);
    float a0 = g_logit[(size_t)w * 2]     / (g_sum[dst * 2]     + 1e-16f);
    float a1 = g_logit[(size_t)w * 2 + 1] / (g_sum[dst * 2 + 1] + 1e-16f);
    const float4* v4 = (const float4*)(g_v + (size_t)src * HD);
    float4 va = v4[lane];
    float4 vb = v4[lane + 32];
    float* ag = g_agg + (size_t)dst * HD;
    red4(ag + lane * 4,      va.x * a0, va.y * a0, va.z * a0, va.w * a0);
    red4(ag + DD + lane * 4, vb.x * a1, vb.y * a1, vb.z * a1, vb.w * a1);
}

// ---------------- fold skip into classifier: wsc = wskip@wc, bsc = bskip@wc + bc ----------------
// needs DD*OUTD + OUTD = 8256 threads -> 33 blocks of 256 (the r12/r15 bug was 17 blocks)
__global__ void k_fusew(const float* __restrict__ wskip, const float* __restrict__ bskip,
                        const float* __restrict__ wc, const float* __restrict__ bc) {
    int tid = blockIdx.x * blockDim.x + threadIdx.x;
    if (tid < DD * OUTD) {
        int i = tid >> 6, o = tid & 63;
        float s = 0.f;
        for (int p = 0; p < HD; ++p) s += wskip[i * HD + p] * wc[p * OUTD + o];
        g_wsc[tid] = s;
    } else if (tid < DD * OUTD + OUTD) {
        int o = tid - DD * OUTD;
        float s = bc[o];
        for (int p = 0; p < HD; ++p) s += bskip[p] * wc[p * OUTD + o];
        g_bsc[o] = s;
    }
}

// ---------------- final: out = agg @ wc + node_mem @ wsc + bsc ----------------
__global__ __launch_bounds__(256) void k_final(const float* __restrict__ wc,
                                               float* __restrict__ out) {
    __shared__ __align__(16) float As[32 * HD];  // 32 KB
    const int t = threadIdx.x;
    const int nb = blockIdx.x * 32;
    const int pq = t & 15, mq = t >> 4;
    const int p0 = pq * 4, m0 = mq * 2;

    u64 acc[2][2] = {{0ull,0ull},{0ull,0ull}};

    // stage 1: agg @ wc
    for (int idx = t; idx < 32 * HD; idx += 256)
        As[idx] = g_agg[(size_t)nb * HD + idx];
    __syncthreads();
    #pragma unroll 4
    for (int k = 0; k < HD; ++k) {
        ulonglong2 wv = ldw2(wc + k * OUTD + p0);
        #pragma unroll
        for (int i = 0; i < 2; ++i) {
            u64 x2 = pack2(As[(m0 + i) * HD + k]);
            fma2(acc[i][0], x2, wv.x);
            fma2(acc[i][1], x2, wv.y);
        }
    }
    __syncthreads();

    // stage 2: node_mem @ wsc
    for (int idx = t; idx < 32 * DD; idx += 256)
        As[idx] = g_node_mem[(size_t)nb * DD + idx];
    __syncthreads();
    #pragma unroll 4
    for (int k = 0; k < DD; ++k) {
        ulonglong2 wv = ldw2(g_wsc + k * OUTD + p0);
        #pragma unroll
        for (int i = 0; i < 2; ++i) {
            u64 x2 = pack2(As[(m0 + i) * DD + k]);
            fma2(acc[i][0], x2, wv.x);
            fma2(acc[i][1], x2, wv.y);
        }
    }

    float b[4]; *(float4*)b = ld4(g_bsc + p0);
    #pragma unroll
    for (int i = 0; i < 2; ++i) {
        float2 lo = unpack2(acc[i][0]), hi = unpack2(acc[i][1]);
        float o[4] = { lo.x + b[0], lo.y + b[1], hi.x + b[2], hi.y + b[3] };
        *(float4*)&out[(size_t)(nb + m0 + i) * OUTD + p0] = *(float4*)o;
    }
}

// ---------------- launch ----------------
extern "C" void kernel_launch(void* const* d_in, const int* in_sizes, int n_in,
                              void* d_out, int out_size) {
    const void* ei  = d_in[0];
    const float* edge_attr = (const float*)d_in[1];
    // d_in[2] = edge_time (unused)
    const float* memory = (const float*)d_in[3];
    const float* w1 = (const float*)d_in[4];
    const float* b1 = (const float*)d_in[5];
    const float* w2 = (const float*)d_in[6];
    const float* b2 = (const float*)d_in[7];
    const float* gwih = (const float*)d_in[8];
    const float* gwhh = (const float*)d_in[9];
    const float* gbih = (const float*)d_in[10];
    const float* gbhh = (const float*)d_in[11];
    const float* wq = (const float*)d_in[12];
    const float* bq = (const float*)d_in[13];
    const float* wk = (const float*)d_in[14];
    const float* bk = (const float*)d_in[15];
    const float* wv = (const float*)d_in[16];
    const float* bv = (const float*)d_in[17];
    const float* wskip = (const float*)d_in[18];
    const float* bskip = (const float*)d_in[19];
    const float* wc = (const float*)d_in[20];
    const float* bc = (const float*)d_in[21];
    float* out = (float*)d_out;

    // order chosen so k_node is the 4th launch (the slot ncu captures)
    k_detect<<<1, 256>>>(ei);                                                 // 1
    k_init<<<(NN * HD + 255) / 256, 256>>>();                                 // 2
    k_winner_t<<<(EE + 255) / 256, 256>>>(ei, gwih, gwhh);                    // 3 (winner + transpose)
    k_node<<<NN / 16, 256>>>(ei, edge_attr, memory, w1, b1, w2, b2, gbih, gbhh); // 4 <- profiled

    dim3 gq((NN + 63) / 64, HD / 64);
    k_gemm<<<gq, 256>>>(wq, bq, 0);                                           // 5
    k_gemm<<<gq, 256>>>(wk, bk, 1);                                           // 6
    k_gemm<<<gq, 256>>>(wv, bv, 2);                                           // 7

    k_att_a<<<EE / 8, 256>>>(ei);                                             // 8
    k_att_c<<<EE / 8, 256>>>(ei);                                             // 9

    k_fusew<<<(DD * OUTD + OUTD + 255) / 256, 256>>>(wskip, bskip, wc, bc);   // 10 (33 blocks)
    k_final<<<NN / 32, 256>>>(wc, out);                                       // 11
}